// round 8
// baseline (speedup 1.0000x reference)
#include <cuda_runtime.h>
#include <cuda_bf16.h>
#include <math.h>

#define B_ROWS   2048
#define C_COLS   32000
#define TPB      256
#define QUARTERS 4
#define Q4       (C_COLS / 4 / QUARTERS)      // 2000 float4 per quarter
#define NGRID    (B_ROWS * QUARTERS)          // 8192 CTAs

__device__ float g_part_h[NGRID];
__device__ int   g_part_c[NGRID];
__device__ unsigned int g_done;               // zero-init; last CTA resets each run

// H(n): exact for small n, asymptotic otherwise (err < 1e-9; tolerance 1e-3).
__device__ __forceinline__ float harmonic(int n) {
    if (n <= 0) return 0.0f;
    if (n < 32) {
        float h = 0.0f;
        #pragma unroll 1
        for (int i = 1; i <= n; ++i) h += 1.0f / (float)i;
        return h;
    }
    const float gamma = 0.57721566490153286f;
    float x = (float)n;
    float inv = 1.0f / x;
    float inv2 = inv * inv;
    return logf(x) + gamma + 0.5f * inv - (1.0f / 12.0f) * inv2
           + (1.0f / 120.0f) * inv2 * inv2;
}

__global__ void __launch_bounds__(TPB) fused_kernel(const float* __restrict__ scores,
                                                    const int* __restrict__ targets,
                                                    float* __restrict__ out) {
    __shared__ float s_hs[TPB / 32];
    __shared__ int   s_cnt[TPB / 32];
    __shared__ bool  s_last;

    const int tid = threadIdx.x;
    const int row = blockIdx.x >> 2;
    const int q   = blockIdx.x & 3;

    const float* rowp = scores + (size_t)row * C_COLS;
    const int t = targets[row];
    const float gt = __ldg(rowp + t);          // same address across block -> broadcast
    const float c  = gt - 1.0f;                // hinge: relu(v - c)

    const float4* q4 = reinterpret_cast<const float4*>(rowp) + q * Q4;

    float hs0 = 0.0f, hs1 = 0.0f;
    int cnt = 0;
    #pragma unroll 4
    for (int i = tid; i < Q4; i += TPB) {      // 2000 float4s: 7-8 iters/thread
        float4 v = q4[i];
        cnt += (v.x > gt) + (v.y > gt) + (v.z > gt) + (v.w > gt);
        hs0 += fmaxf(v.x - c, 0.0f);
        hs1 += fmaxf(v.y - c, 0.0f);
        hs0 += fmaxf(v.z - c, 0.0f);
        hs1 += fmaxf(v.w - c, 0.0f);
    }
    float hs = hs0 + hs1;

    #pragma unroll
    for (int off = 16; off > 0; off >>= 1) {
        hs  += __shfl_down_sync(0xFFFFFFFFu, hs,  off);
        cnt += __shfl_down_sync(0xFFFFFFFFu, cnt, off);
    }
    const int wid = tid >> 5;
    const int lid = tid & 31;
    if (lid == 0) { s_hs[wid] = hs; s_cnt[wid] = cnt; }
    __syncthreads();

    if (tid == 0) {
        float hsum = 0.0f;
        int   csum = 0;
        #pragma unroll
        for (int w = 0; w < TPB / 32; ++w) { hsum += s_hs[w]; csum += s_cnt[w]; }
        g_part_h[blockIdx.x] = hsum;           // includes the target's relu(1)=1 in one quarter
        g_part_c[blockIdx.x] = csum;
    }

    // ---- last-CTA deterministic final reduction over all 8192 partials ----
    if (tid == 0) {
        __threadfence();                       // publish partials
        unsigned int n = atomicAdd(&g_done, 1u);
        s_last = (n == NGRID - 1);
    }
    __syncthreads();

    if (s_last) {
        __shared__ float s_red[TPB];
        float acc = 0.0f;
        // each thread: 8 rows, fixed order -> deterministic
        #pragma unroll 1
        for (int r = tid; r < B_ROWS; r += TPB) {
            float hsum = 0.0f;
            int   csum = 0;
            #pragma unroll
            for (int k = 0; k < QUARTERS; ++k) {
                hsum += g_part_h[r * QUARTERS + k];
                csum += g_part_c[r * QUARTERS + k];
            }
            float hinge = hsum - 1.0f;         // remove target's own contribution
            int rank = csum;                   // #(scores > gt)
            float weight = (rank == 0) ? 0.0f : harmonic(rank) / (float)rank;
            acc += weight * hinge;
        }
        s_red[tid] = acc;
        __syncthreads();
        #pragma unroll
        for (int off = TPB / 2; off > 0; off >>= 1) {
            if (tid < off) s_red[tid] += s_red[tid + off];
            __syncthreads();
        }
        if (tid == 0) {
            out[0] = s_red[0] / (float)B_ROWS;
            g_done = 0;                        // reset for next graph replay
        }
    }
}

extern "C" void kernel_launch(void* const* d_in, const int* in_sizes, int n_in,
                              void* d_out, int out_size) {
    const float* scores  = (const float*)d_in[0];
    const int*   targets = (const int*)d_in[1];
    float* out = (float*)d_out;

    fused_kernel<<<NGRID, TPB>>>(scores, targets, out);
}

// round 9
// speedup vs baseline: 1.3146x; 1.3146x over previous
#include <cuda_runtime.h>
#include <cuda_bf16.h>
#include <math.h>

#define B_ROWS 2048
#define C_COLS 32000
#define TPB    256
#define N4     (C_COLS / 4)          // 8000 float4 per row
#define GRID   (B_ROWS / 2)          // 1024 CTAs, 2 adjacent rows each -> single wave

__device__ float g_row_loss[B_ROWS];
__device__ unsigned int g_done;      // zero-init; last CTA resets each run

// H(n): exact for small n, asymptotic otherwise (err < 1e-9; tolerance 1e-3).
__device__ __forceinline__ float harmonic(int n) {
    if (n <= 0) return 0.0f;
    if (n < 32) {
        float h = 0.0f;
        #pragma unroll 1
        for (int i = 1; i <= n; ++i) h += 1.0f / (float)i;
        return h;
    }
    const float gamma = 0.57721566490153286f;
    float x = (float)n;
    float inv = 1.0f / x;
    float inv2 = inv * inv;
    return logf(x) + gamma + 0.5f * inv - (1.0f / 12.0f) * inv2
           + (1.0f / 120.0f) * inv2 * inv2;
}

__global__ void __launch_bounds__(TPB, 8) fused_kernel(const float* __restrict__ scores,
                                                       const int* __restrict__ targets,
                                                       float* __restrict__ out) {
    __shared__ float s_hs[2][TPB / 32];
    __shared__ int   s_cnt[2][TPB / 32];
    __shared__ bool  s_last;

    const int tid = threadIdx.x;
    const int b0 = blockIdx.x * 2;
    const int b1 = b0 + 1;

    // Hoist BOTH scalar chains to the top: they overlap row-0 streaming.
    const int t0 = __ldg(&targets[b0]);
    const int t1 = __ldg(&targets[b1]);
    const float* row0 = scores + (size_t)b0 * C_COLS;
    const float* row1 = scores + (size_t)b1 * C_COLS;
    const float gt0 = __ldg(row0 + t0);
    const float gt1 = __ldg(row1 + t1);
    const float c0 = gt0 - 1.0f;
    const float c1 = gt1 - 1.0f;

    const float4* r0 = reinterpret_cast<const float4*>(row0);
    const float4* r1 = reinterpret_cast<const float4*>(row1);

    // ---- stream row 0 (no reduction yet; partials live in registers) ----
    float a0 = 0.0f, a1 = 0.0f;
    int cnt0 = 0;
    #pragma unroll 4
    for (int i = tid; i < N4; i += TPB) {
        float4 v = r0[i];
        cnt0 += (v.x > gt0) + (v.y > gt0) + (v.z > gt0) + (v.w > gt0);
        a0 += fmaxf(v.x - c0, 0.0f);
        a1 += fmaxf(v.y - c0, 0.0f);
        a0 += fmaxf(v.z - c0, 0.0f);
        a1 += fmaxf(v.w - c0, 0.0f);
    }
    float hs0 = a0 + a1;

    // ---- stream row 1 immediately (gt1 already resident) ----
    float d0 = 0.0f, d1 = 0.0f;
    int cnt1 = 0;
    #pragma unroll 4
    for (int i = tid; i < N4; i += TPB) {
        float4 v = r1[i];
        cnt1 += (v.x > gt1) + (v.y > gt1) + (v.z > gt1) + (v.w > gt1);
        d0 += fmaxf(v.x - c1, 0.0f);
        d1 += fmaxf(v.y - c1, 0.0f);
        d0 += fmaxf(v.z - c1, 0.0f);
        d1 += fmaxf(v.w - c1, 0.0f);
    }
    float hs1 = d0 + d1;

    // ---- one reduction phase for both rows ----
    #pragma unroll
    for (int off = 16; off > 0; off >>= 1) {
        hs0  += __shfl_down_sync(0xFFFFFFFFu, hs0,  off);
        cnt0 += __shfl_down_sync(0xFFFFFFFFu, cnt0, off);
        hs1  += __shfl_down_sync(0xFFFFFFFFu, hs1,  off);
        cnt1 += __shfl_down_sync(0xFFFFFFFFu, cnt1, off);
    }
    const int wid = tid >> 5;
    const int lid = tid & 31;
    if (lid == 0) {
        s_hs[0][wid] = hs0; s_cnt[0][wid] = cnt0;
        s_hs[1][wid] = hs1; s_cnt[1][wid] = cnt1;
    }
    __syncthreads();

    if (tid < 2) {   // thread 0 -> row b0, thread 1 -> row b1
        float hsum = 0.0f;
        int   csum = 0;
        #pragma unroll
        for (int w = 0; w < TPB / 32; ++w) { hsum += s_hs[tid][w]; csum += s_cnt[tid][w]; }
        float hinge = hsum - 1.0f;        // remove target's own relu(1)=1
        int rank = csum;                  // #(scores > gt)
        float weight = (rank == 0) ? 0.0f : harmonic(rank) / (float)rank;
        g_row_loss[b0 + tid] = weight * hinge;
    }

    // ---- last-CTA deterministic final reduction ----
    if (tid == 0) {
        __threadfence();                  // publish g_row_loss
        unsigned int n = atomicAdd(&g_done, 1u);
        s_last = (n == GRID - 1);
    }
    __syncthreads();

    if (s_last) {
        __shared__ float s_red[TPB];
        float acc = 0.0f;
        #pragma unroll
        for (int i = tid; i < B_ROWS; i += TPB) acc += g_row_loss[i];
        s_red[tid] = acc;
        __syncthreads();
        #pragma unroll
        for (int off = TPB / 2; off > 0; off >>= 1) {
            if (tid < off) s_red[tid] += s_red[tid + off];
            __syncthreads();
        }
        if (tid == 0) {
            out[0] = s_red[0] / (float)B_ROWS;
            g_done = 0;                   // reset for next graph replay
        }
    }
}

extern "C" void kernel_launch(void* const* d_in, const int* in_sizes, int n_in,
                              void* d_out, int out_size) {
    const float* scores  = (const float*)d_in[0];
    const int*   targets = (const int*)d_in[1];
    float* out = (float*)d_out;

    fused_kernel<<<GRID, TPB>>>(scores, targets, out);
}